// round 16
// baseline (speedup 1.0000x reference)
#include <cuda_runtime.h>
#include <math.h>
#include <stdint.h>

// ---------------------------------------------------------------------------
// RG-LRU forward, T=8192, D_MODEL=768, D_RNN=1024, KW=4.
// Mega-merged GEMM1/conv kernel: one 1536-CTA launch with three duties
// (bb tiles -> ab tiles -> conv tiles); conv tiles wait on bb row-block flags.
// Scans: NCHK=256/CLEN=32. All mainloops race-free split-tail.
// ---------------------------------------------------------------------------

#define T_LEN 8192
#define DM    768
#define DR    1024
#define NCHK  256
#define CLEN  32

#define NSTAGE 3
#define BKF    32

// scratch
__device__ float g_ab[T_LEN * DR];
__device__ float g_bbp[(T_LEN + 3) * DR];   // 3 zero rows + bb
__device__ float g_bcr[T_LEN * DR];         // conv out, tf32-rounded
__device__ float g_at[T_LEN * DR];
__device__ float g_gx[T_LEN * DR];
__device__ float g_z[T_LEN * DR];
__device__ float g_wc[DR * DR * 4];
__device__ float g_xr[T_LEN * DM];
__device__ float g_w1r[2 * DR * DM];
__device__ float g_wrgp[2 * DR * DR];
__device__ float g_brgp[2 * DR];
__device__ float g_woutr[DM * DR];
__device__ float g_lam[DR];
__device__ float g_P[NCHK * DR];
__device__ float g_L[NCHK * DR];
__device__ float g_carry[NCHK * DR];
__device__ int   g_flag[64];                // bb row-block completion counters

// ---------------- helpers ----------------
__device__ __forceinline__ uint32_t smem_u32(const void* p) {
    uint32_t a;
    asm("{ .reg .u64 t; cvta.to.shared.u64 t, %1; cvt.u32.u64 %0, t; }" : "=r"(a) : "l"(p));
    return a;
}
__device__ __forceinline__ uint32_t f2tf32(float f) {
    uint32_t u; asm("cvt.rna.tf32.f32 %0, %1;" : "=r"(u) : "f"(f)); return u;
}
__device__ __forceinline__ float roundtf(float f) { return __uint_as_float(f2tf32(f)); }

__device__ __forceinline__ float sigm(float x) {
    return __fdividef(1.0f, 1.0f + __expf(-x));
}
__device__ __forceinline__ float gelu_f(float x) {
    float x3 = x * x * x;
    float v  = 1.5957691216057308f * (x + 0.044715f * x3);
    return x * sigm(v);
}

#define SW128(o) ((o) ^ ((((uint32_t)(o)) >> 3) & 0x70u))

__device__ __forceinline__ void cp16(uint32_t dst, const void* src) {
    asm volatile("cp.async.cg.shared.global [%0], [%1], 16;\n"
                 :: "r"(dst), "l"(src) : "memory");
}
__device__ __forceinline__ void cp_commit() {
    asm volatile("cp.async.commit_group;" ::: "memory");
}
__device__ __forceinline__ void ldsm4(uint32_t r[4], uint32_t addr) {
    asm volatile("ldmatrix.sync.aligned.m8n8.x4.shared.b16 {%0,%1,%2,%3}, [%4];"
                 : "=r"(r[0]), "=r"(r[1]), "=r"(r[2]), "=r"(r[3]) : "r"(addr));
}
__device__ __forceinline__ void mma_tf32(float d[4], const uint32_t a[4],
                                         const uint32_t b[2], const float c[4]) {
    asm volatile(
        "mma.sync.aligned.m16n8k8.row.col.f32.tf32.tf32.f32 "
        "{%0,%1,%2,%3}, {%4,%5,%6,%7}, {%8,%9}, {%10,%11,%12,%13};\n"
        : "=f"(d[0]), "=f"(d[1]), "=f"(d[2]), "=f"(d[3])
        : "r"(a[0]), "r"(a[1]), "r"(a[2]), "r"(a[3]),
          "r"(b[0]), "r"(b[1]),
          "f"(c[0]), "f"(c[1]), "f"(c[2]), "f"(c[3]));
}

// ---------------------------------------------------------------------------
// Variant A (short-K GEMMs): 256 threads, 4x2 warps, 32x(BN/2) warp tiles.
//   EPI 0: raw+bias   EPI 4: fused gates
// ---------------------------------------------------------------------------
template <int EPI, int BN>
__global__ __launch_bounds__(256, 2) void tgemm(
    const float* __restrict__ A, const float* __restrict__ B,
    const float* __restrict__ bias, float* __restrict__ C,
    float* __restrict__ C2, const float* __restrict__ Xbc,
    const float* __restrict__ lam, int M, int N, int K)
{
    constexpr int NI = BN / 16;
    constexpr int NP = BN / 32;
    constexpr int ABYTES = 128 * BKF * 4;
    constexpr int BBYTES = BN * BKF * 4;
    constexpr int SBYTES = ABYTES + BBYTES;

    extern __shared__ char dynsm[];
    const uint32_t sb = (smem_u32(dynsm) + 1023u) & ~1023u;

    const int tid  = threadIdx.x;
    const int lane = tid & 31;
    const int wid  = tid >> 5;
    const int bm   = blockIdx.y * 128;
    const int bn   = blockIdx.x * BN;
    const int wm   = (wid >> 1) * 32;
    const int wn   = (wid & 1) * (BN / 2);
    const int qr   = lane >> 2;
    const int qc   = lane & 3;

    const int arow  = wm + (lane & 15);
    const int ahalf = (lane >> 4) & 1;
    const int brow  = wn + (lane & 7) + ((lane >> 4) << 3);
    const int bhalf = (lane >> 3) & 1;

    float acc[2][NI][4];
#pragma unroll
    for (int mi = 0; mi < 2; mi++)
#pragma unroll
        for (int ni = 0; ni < NI; ni++)
#pragma unroll
            for (int r = 0; r < 4; r++) acc[mi][ni][r] = 0.0f;

    const int nch = K / BKF;

    auto issue_chunk = [&](int c) {
        const int s = c % NSTAGE;
        const uint32_t abase = sb + s * SBYTES;
        const uint32_t bbase = abase + ABYTES;
        const int k0 = c * BKF;
#pragma unroll
        for (int q = 0; q < 4; q++) {
            int id  = tid + q * 256;
            int row = id >> 3;
            int c16 = id & 7;
            cp16(abase + SW128(row * 128 + c16 * 16),
                 A + (size_t)(bm + row) * K + k0 + c16 * 4);
        }
#pragma unroll
        for (int q = 0; q < NP; q++) {
            int id  = tid + q * 256;
            int row = id >> 3;
            int c16 = id & 7;
            cp16(bbase + SW128(row * 128 + c16 * 16),
                 B + (size_t)(bn + row) * K + k0 + c16 * 4);
        }
        cp_commit();
    };

    auto compute = [&](int s) {
        const uint32_t abase = sb + s * SBYTES;
        const uint32_t bbase = abase + ABYTES;
#pragma unroll
        for (int kb = 0; kb < 4; kb++) {
            uint32_t af[2][4];
#pragma unroll
            for (int mi = 0; mi < 2; mi++)
                ldsm4(af[mi], abase + SW128((arow + mi * 16) * 128 + kb * 32 + ahalf * 16));
            uint32_t bf[NP][4];
#pragma unroll
            for (int p = 0; p < NP; p++)
                ldsm4(bf[p], bbase + SW128((brow + p * 16) * 128 + kb * 32 + bhalf * 16));
#pragma unroll
            for (int mi = 0; mi < 2; mi++)
#pragma unroll
                for (int ni = 0; ni < NI; ni++)
                    mma_tf32(acc[mi][ni], af[mi], &bf[ni >> 1][(ni & 1) * 2], acc[mi][ni]);
        }
    };

    // mainloop: split tail (race-free)
    issue_chunk(0);
    issue_chunk(1);
    for (int c = 0; c < nch - 1; c++) {
        asm volatile("cp.async.wait_group %0;" :: "n"(1) : "memory");
        __syncthreads();
        if (c + 2 < nch) issue_chunk(c + 2);
        compute(c % NSTAGE);
    }
    asm volatile("cp.async.wait_group %0;" :: "n"(0) : "memory");
    __syncthreads();
    compute((nch - 1) % NSTAGE);

#pragma unroll
    for (int mi = 0; mi < 2; mi++) {
#pragma unroll
        for (int ni = 0; ni < NI; ni++) {
#pragma unroll
            for (int half = 0; half < 2; half++) {
                int m = bm + wm + mi * 16 + qr + half * 8;
                int n = bn + wn + ni * 8 + 2 * qc;
                if (EPI == 0) {
                    C[(size_t)m * N + n]     = acc[mi][ni][half * 2 + 0] + bias[n];
                    C[(size_t)m * N + n + 1] = acc[mi][ni][half * 2 + 1] + bias[n + 1];
                } else {  // EPI == 4 : fused gate pair (inp, rec) for channel n>>1
                    float v0  = acc[mi][ni][half * 2 + 0] + bias[n];
                    float v1  = acc[mi][ni][half * 2 + 1] + bias[n + 1];
                    int ch    = n >> 1;
                    float inp = sigm(v0);
                    float rec = sigm(v1);
                    float a   = __expf(lam[ch] * rec);
                    float gx  = sqrtf(fmaxf(1.0f - a * a, 0.0f)) * inp *
                                Xbc[(size_t)m * DR + ch];
                    C[(size_t)m * DR + ch]  = a;
                    C2[(size_t)m * DR + ch] = gx;
                }
            }
        }
    }
}

// ---------------------------------------------------------------------------
// Mega-merged kernel: 128 threads, 2x2 warps, 64x64 warp tiles. 1536 CTAs:
//   duty 0 (bid    0..511 ): bb tile  (A=xr K=768, B=w1b; round -> g_bbp; flag)
//   duty 1 (bid  512..1023): ab tile  (A=xr K=768, B=w1a; bias+gelu -> g_ab)
//   duty 2 (bid 1024..1535): conv tile(A=padded bb K=4096, B=wc; waits flags)
// ---------------------------------------------------------------------------
__global__ __launch_bounds__(128, 2) void tgemm_merged(
    const float* __restrict__ Axr, const float* __restrict__ Abbp,
    const float* __restrict__ Bwc, const float* __restrict__ Bw1,
    const float* __restrict__ b1,
    float* __restrict__ Cbb, float* __restrict__ Cab,
    float* __restrict__ Cbc, int* __restrict__ flags)
{
    constexpr int SBYTES = 2 * 128 * BKF * 4;
    extern __shared__ char dynsm[];
    const uint32_t sb = (smem_u32(dynsm) + 1023u) & ~1023u;

    const int bid  = blockIdx.x;
    const int duty = (bid < 512) ? 0 : ((bid < 1024) ? 1 : 2);
    const int tile = bid - ((duty == 0) ? 0 : ((duty == 1) ? 512 : 1024));
    const int bn   = (tile & 7) * 128;
    const int bm   = (tile >> 3) * 128;
    const int K    = (duty == 2) ? (DR * 4) : DM;
    const int Alda = (duty == 2) ? DR : DM;
    const float* Abase = (duty == 2) ? Abbp : Axr;
    const float* B = (duty == 0) ? (Bw1 + (size_t)DR * DM)
                   : ((duty == 1) ? Bw1 : Bwc);

    const int tid  = threadIdx.x;
    const int wid  = tid >> 5;
    const int lane = tid & 31;
    const int wm   = (wid >> 1) * 64;
    const int wn   = (wid & 1) * 64;
    const int qr   = lane >> 2;
    const int qc   = lane & 3;

    const int arow  = wm + (lane & 15);
    const int ahalf = (lane >> 4) & 1;
    const int brow  = wn + (lane & 7) + ((lane >> 4) << 3);
    const int bhalf = (lane >> 3) & 1;

    // conv tiles wait for the bb row-blocks they read (bm-3 .. bm+127)
    if (duty == 2) {
        if (tid == 0) {
            int bmb = bm >> 7;
            while (atomicAdd(&flags[bmb], 0) < 8) __nanosleep(64);
            if (bmb > 0)
                while (atomicAdd(&flags[bmb - 1], 0) < 8) __nanosleep(64);
        }
        __syncthreads();
    }

    float acc[4][8][4];
#pragma unroll
    for (int mi = 0; mi < 4; mi++)
#pragma unroll
        for (int ni = 0; ni < 8; ni++)
#pragma unroll
            for (int r = 0; r < 4; r++) acc[mi][ni][r] = 0.0f;

    const int nch = K / BKF;

    auto issue_chunk = [&](int c) {
        const int s = c % NSTAGE;
        const uint32_t abase = sb + s * SBYTES;
        const uint32_t bbase = abase + 128 * BKF * 4;
        const int k0 = c * BKF;
#pragma unroll
        for (int q = 0; q < 8; q++) {
            int id  = tid + q * 128;
            int row = id >> 3;
            int c16 = id & 7;
            cp16(abase + SW128(row * 128 + c16 * 16),
                 Abase + (size_t)(bm + row) * Alda + k0 + c16 * 4);
            cp16(bbase + SW128(row * 128 + c16 * 16),
                 B + (size_t)(bn + row) * K + k0 + c16 * 4);
        }
        cp_commit();
    };

    auto compute = [&](int s) {
        const uint32_t abase = sb + s * SBYTES;
        const uint32_t bbase = abase + 128 * BKF * 4;
#pragma unroll
        for (int kb = 0; kb < 4; kb++) {
            uint32_t af[4][4];
#pragma unroll
            for (int mi = 0; mi < 4; mi++)
                ldsm4(af[mi], abase + SW128((arow + mi * 16) * 128 + kb * 32 + ahalf * 16));
            uint32_t bf[4][4];
#pragma unroll
            for (int p = 0; p < 4; p++)
                ldsm4(bf[p], bbase + SW128((brow + p * 16) * 128 + kb * 32 + bhalf * 16));
#pragma unroll
            for (int mi = 0; mi < 4; mi++)
#pragma unroll
                for (int ni = 0; ni < 8; ni++)
                    mma_tf32(acc[mi][ni], af[mi], &bf[ni >> 1][(ni & 1) * 2], acc[mi][ni]);
        }
    };

    // mainloop: issue-first + split tail (race-free)
    issue_chunk(0);
    issue_chunk(1);
    for (int c = 0; c < nch - 1; c++) {
        asm volatile("cp.async.wait_group %0;" :: "n"(1) : "memory");
        __syncthreads();
        if (c + 2 < nch) issue_chunk(c + 2);
        compute(c % NSTAGE);
    }
    asm volatile("cp.async.wait_group %0;" :: "n"(0) : "memory");
    __syncthreads();
    compute((nch - 1) % NSTAGE);

    // epilogue
#pragma unroll
    for (int mi = 0; mi < 4; mi++) {
#pragma unroll
        for (int ni = 0; ni < 8; ni++) {
#pragma unroll
            for (int half = 0; half < 2; half++) {
                int m = bm + wm + mi * 16 + qr + half * 8;
                int n = bn + wn + ni * 8 + 2 * qc;
                float v0 = acc[mi][ni][half * 2 + 0];
                float v1 = acc[mi][ni][half * 2 + 1];
                if (duty == 0) {
                    Cbb[(size_t)(m + 3) * DR + n]     = roundtf(v0 + b1[DR + n]);
                    Cbb[(size_t)(m + 3) * DR + n + 1] = roundtf(v1 + b1[DR + n + 1]);
                } else if (duty == 1) {
                    Cab[(size_t)m * DR + n]     = gelu_f(v0 + b1[n]);
                    Cab[(size_t)m * DR + n + 1] = gelu_f(v1 + b1[n + 1]);
                } else {
                    Cbc[(size_t)m * DR + n]     = roundtf(v0);
                    Cbc[(size_t)m * DR + n + 1] = roundtf(v1);
                }
            }
        }
    }

    // bb tiles: publish completion (gpu-scope release)
    if (duty == 0) {
        __threadfence();
        __syncthreads();
        if (tid == 0) atomicAdd(&flags[bm >> 7], 1);
    }
}

// ---------------------------------------------------------------------------
// prep (single kernel) — also resets bb flags for graph replay
__global__ void prep_kernel(const float* __restrict__ wrg,
                            const float* __restrict__ brg,
                            const float* __restrict__ Lambda,
                            const float* __restrict__ convw,
                            const float* __restrict__ x,
                            const float* __restrict__ w1,
                            const float* __restrict__ wout) {
    int gid = blockIdx.x * blockDim.x + threadIdx.x;
    if (gid < 64)     g_flag[gid] = 0;
    if (gid < 2 * DR) g_brgp[gid] = brg[(gid & 1) ? (DR + (gid >> 1)) : (gid >> 1)];
    if (gid < DR)     g_lam[gid]  = -8.0f * log1pf(expf(Lambda[gid]));
    if (gid < 2 * DR * DR / 4) {
        int r  = gid >> 8;
        int k4 = gid & 255;
        int srcr = (r & 1) ? (DR + (r >> 1)) : (r >> 1);
        float4 v = *reinterpret_cast<const float4*>(&wrg[(size_t)srcr * DR + k4 * 4]);
        v.x = roundtf(v.x); v.y = roundtf(v.y); v.z = roundtf(v.z); v.w = roundtf(v.w);
        *reinterpret_cast<float4*>(&g_wrgp[(size_t)r * DR + k4 * 4]) = v;
    }
    if (gid < DR * DR) {
        int o = gid >> 10;
        int i = gid & 1023;
        float4 v = *reinterpret_cast<const float4*>(&convw[(size_t)gid * 4]);
        size_t base = (size_t)o * 4096 + i;
        g_wc[base]        = roundtf(v.x);
        g_wc[base + 1024] = roundtf(v.y);
        g_wc[base + 2048] = roundtf(v.z);
        g_wc[base + 3072] = roundtf(v.w);
    }
    {
        const int nx = T_LEN * DM / 4, n1 = 2 * DR * DM / 4, n2 = DM * DR / 4;
        const float4* s = nullptr; float4* d = nullptr; int i = 0;
        if (gid < nx)                { s = (const float4*)x;    d = (float4*)g_xr;    i = gid; }
        else if (gid < nx + n1)      { s = (const float4*)w1;   d = (float4*)g_w1r;   i = gid - nx; }
        else if (gid < nx + n1 + n2) { s = (const float4*)wout; d = (float4*)g_woutr; i = gid - nx - n1; }
        if (s) {
            float4 v = s[i];
            v.x = roundtf(v.x); v.y = roundtf(v.y); v.z = roundtf(v.z); v.w = roundtf(v.w);
            d[i] = v;
        }
    }
}

// ---- 3-phase chunked linear scan (float4 over channels; 256 chunks of 32) ----
__global__ void scan_phaseA_kernel() {
    int g = blockIdx.x * blockDim.x + threadIdx.x;
    if (g >= NCHK * DR / 4) return;
    int c4 = (g & (DR / 4 - 1)) * 4;
    int ch = g / (DR / 4);
    size_t base = (size_t)ch * CLEN * DR + c4;
    float4 P = make_float4(1.f, 1.f, 1.f, 1.f);
    float4 L = make_float4(0.f, 0.f, 0.f, 0.f);
#pragma unroll 4
    for (int t = 0; t < CLEN; t++) {
        float4 a = *reinterpret_cast<const float4*>(&g_at[base + (size_t)t * DR]);
        float4 x = *reinterpret_cast<const float4*>(&g_gx[base + (size_t)t * DR]);
        L.x = fmaf(a.x, L.x, x.x); L.y = fmaf(a.y, L.y, x.y);
        L.z = fmaf(a.z, L.z, x.z); L.w = fmaf(a.w, L.w, x.w);
        P.x *= a.x; P.y *= a.y; P.z *= a.z; P.w *= a.w;
    }
    *reinterpret_cast<float4*>(&g_P[ch * DR + c4]) = P;
    *reinterpret_cast<float4*>(&g_L[ch * DR + c4]) = L;
}

__global__ void scan_phaseB_kernel() {
    int c4 = (blockIdx.x * blockDim.x + threadIdx.x) * 4;
    if (c4 >= DR) return;
    float4 carry = make_float4(0.f, 0.f, 0.f, 0.f);
    for (int ch = 0; ch < NCHK; ch++) {
        *reinterpret_cast<float4*>(&g_carry[ch * DR + c4]) = carry;
        float4 P = *reinterpret_cast<const float4*>(&g_P[ch * DR + c4]);
        float4 L = *reinterpret_cast<const float4*>(&g_L[ch * DR + c4]);
        carry.x = fmaf(P.x, carry.x, L.x); carry.y = fmaf(P.y, carry.y, L.y);
        carry.z = fmaf(P.z, carry.z, L.z); carry.w = fmaf(P.w, carry.w, L.w);
    }
}

__global__ void scan_phaseC_kernel() {
    int g = blockIdx.x * blockDim.x + threadIdx.x;
    if (g >= NCHK * DR / 4) return;
    int c4 = (g & (DR / 4 - 1)) * 4;
    int ch = g / (DR / 4);
    size_t base = (size_t)ch * CLEN * DR + c4;
    float4 h = *reinterpret_cast<const float4*>(&g_carry[ch * DR + c4]);
#pragma unroll 4
    for (int t = 0; t < CLEN; t++) {
        size_t o = base + (size_t)t * DR;
        float4 a  = *reinterpret_cast<const float4*>(&g_at[o]);
        float4 x  = *reinterpret_cast<const float4*>(&g_gx[o]);
        float4 ab = *reinterpret_cast<const float4*>(&g_ab[o]);
        h.x = fmaf(a.x, h.x, x.x); h.y = fmaf(a.y, h.y, x.y);
        h.z = fmaf(a.z, h.z, x.z); h.w = fmaf(a.w, h.w, x.w);
        float4 z;
        z.x = roundtf(ab.x * h.x); z.y = roundtf(ab.y * h.y);
        z.z = roundtf(ab.z * h.z); z.w = roundtf(ab.w * h.w);
        *reinterpret_cast<float4*>(&g_z[o]) = z;
    }
}

// ---------------------------------------------------------------------------
extern "C" void kernel_launch(void* const* d_in, const int* in_sizes, int n_in,
                              void* d_out, int out_size)
{
    const float* x      = (const float*)d_in[0];
    const float* w1     = (const float*)d_in[1];
    const float* b1     = (const float*)d_in[2];
    const float* conv_w = (const float*)d_in[3];
    const float* w_rg   = (const float*)d_in[4];
    const float* b_rg   = (const float*)d_in[5];
    const float* w_out  = (const float*)d_in[6];
    const float* b_out  = (const float*)d_in[7];
    const float* Lambda = (const float*)d_in[8];
    float* out = (float*)d_out;

    float *p_ab, *p_bbp, *p_bcr, *p_at, *p_gx, *p_z, *p_wc;
    float *p_xr, *p_w1r, *p_wrgp, *p_brgp, *p_woutr, *p_lam;
    int   *p_flag;
    cudaGetSymbolAddress((void**)&p_ab,    g_ab);
    cudaGetSymbolAddress((void**)&p_bbp,   g_bbp);
    cudaGetSymbolAddress((void**)&p_bcr,   g_bcr);
    cudaGetSymbolAddress((void**)&p_at,    g_at);
    cudaGetSymbolAddress((void**)&p_gx,    g_gx);
    cudaGetSymbolAddress((void**)&p_z,     g_z);
    cudaGetSymbolAddress((void**)&p_wc,    g_wc);
    cudaGetSymbolAddress((void**)&p_xr,    g_xr);
    cudaGetSymbolAddress((void**)&p_w1r,   g_w1r);
    cudaGetSymbolAddress((void**)&p_wrgp,  g_wrgp);
    cudaGetSymbolAddress((void**)&p_brgp,  g_brgp);
    cudaGetSymbolAddress((void**)&p_woutr, g_woutr);
    cudaGetSymbolAddress((void**)&p_lam,   g_lam);
    cudaGetSymbolAddress((void**)&p_flag,  g_flag);

    const int smem128 = NSTAGE * (128 + 128) * BKF * 4 + 1024;
    const int smem64  = NSTAGE * (128 + 64)  * BKF * 4 + 1024;
    cudaFuncSetAttribute(tgemm_merged,  cudaFuncAttributeMaxDynamicSharedMemorySize, smem128);
    cudaFuncSetAttribute(tgemm<4, 128>, cudaFuncAttributeMaxDynamicSharedMemorySize, smem128);
    cudaFuncSetAttribute(tgemm<0, 64>,  cudaFuncAttributeMaxDynamicSharedMemorySize, smem64);

    // #1 prep (also zeroes bb flags)
    {
        int total = T_LEN * DM / 4 + 2 * DR * DM / 4 + DM * DR / 4;
        int grid  = total > DR * DR ? total : DR * DR;
        prep_kernel<<<(grid + 255) / 256, 256>>>(w_rg, b_rg, Lambda, conv_w, x, w1, w_out);
    }
    // #2 mega-merged: bb (512) -> ab (512) -> conv (512, flag-gated)
    {
        tgemm_merged<<<1536, 128, smem128>>>(p_xr, p_bbp, p_wc, p_w1r, b1,
                                             p_bbp, p_ab, p_bcr, p_flag);
    }
    // #3 gemm3 + fused gates
    {
        dim3 grid((2 * DR) / 128, T_LEN / 128);
        tgemm<4, 128><<<grid, 256, smem128>>>(p_bcr, p_wrgp, p_brgp, p_at, p_gx,
                                              p_bcr, p_lam, T_LEN, 2 * DR, DR);
    }
    scan_phaseA_kernel<<<(NCHK * DR / 4 + 255) / 256, 256>>>();
    scan_phaseB_kernel<<<(DR / 4 + 255) / 256, 256>>>();
    scan_phaseC_kernel<<<(NCHK * DR / 4 + 255) / 256, 256>>>();
    // #7 gemm4 (BN=64)
    {
        dim3 grid(DM / 64, T_LEN / 128);
        tgemm<0, 64><<<grid, 256, smem64>>>(p_z, p_woutr, b_out, out, nullptr,
                                            nullptr, nullptr, T_LEN, DM, DR);
    }
}

// round 17
// speedup vs baseline: 1.0987x; 1.0987x over previous
#include <cuda_runtime.h>
#include <math.h>
#include <stdint.h>

// ---------------------------------------------------------------------------
// RG-LRU forward, T=8192, D_MODEL=768, D_RNN=1024, KW=4.
// conv(GEMM1b(x)) composed into one GEMM'(x) with precomputed weights
// W'[o, tap*768+j] = sum_i conv_w[o,i,tap]*w1b[i,j]  (hi/lo split of w1b).
// R14 numerics (rel_err 6.22e-4) + fixed prep (warp-reduced bias vectors,
// coalesced w1bt) + R15 split-tail mainloops and NCHK=256 scans.
// ---------------------------------------------------------------------------

#define T_LEN 8192
#define DM    768
#define DR    1024
#define NCHK  256
#define CLEN  32

#define NSTAGE 3
#define BKF    32

// scratch
__device__ float g_ab[T_LEN * DR];
__device__ float g_bcr[T_LEN * DR];          // conv out, tf32-rounded (+cb)
__device__ float g_at[T_LEN * DR];
__device__ float g_gx[T_LEN * DR];
__device__ float g_z[T_LEN * DR];
__device__ float g_xpr[(T_LEN + 3) * DM];    // 3 zero rows + rounded x
__device__ float g_w1r[2 * DR * DM];         // rounded w1 (a-half used)
__device__ float g_w1bt[DM * 2048];          // w1b^T: [j][0..1023]=hi, [1024..2047]=lo
__device__ float g_wck[4 * DR * 2048];       // conv tap matrices, duplicated [Wk|Wk]
__device__ float g_wcomb[DR * 3072];         // composed conv weights W'
__device__ float g_wrgp[2 * DR * DR];
__device__ float g_brgp[2 * DR];
__device__ float g_woutr[DM * DR];
__device__ float g_lam[DR];
__device__ float g_cb[DR];                   // (sum_k Wk) @ b1b
__device__ float g_cpart[3 * DR];            // missing-tap bias rows 0..2
__device__ float g_P[NCHK * DR];
__device__ float g_L[NCHK * DR];
__device__ float g_carry[NCHK * DR];

// ---------------- helpers ----------------
__device__ __forceinline__ uint32_t smem_u32(const void* p) {
    uint32_t a;
    asm("{ .reg .u64 t; cvta.to.shared.u64 t, %1; cvt.u32.u64 %0, t; }" : "=r"(a) : "l"(p));
    return a;
}
__device__ __forceinline__ uint32_t f2tf32(float f) {
    uint32_t u; asm("cvt.rna.tf32.f32 %0, %1;" : "=r"(u) : "f"(f)); return u;
}
__device__ __forceinline__ float roundtf(float f) { return __uint_as_float(f2tf32(f)); }

__device__ __forceinline__ float sigm(float x) {
    return __fdividef(1.0f, 1.0f + __expf(-x));
}
__device__ __forceinline__ float gelu_f(float x) {
    float x3 = x * x * x;
    float v  = 1.5957691216057308f * (x + 0.044715f * x3);
    return x * sigm(v);
}

#define SW128(o) ((o) ^ ((((uint32_t)(o)) >> 3) & 0x70u))

__device__ __forceinline__ void cp16(uint32_t dst, const void* src) {
    asm volatile("cp.async.cg.shared.global [%0], [%1], 16;\n"
                 :: "r"(dst), "l"(src) : "memory");
}
__device__ __forceinline__ void cp_commit() {
    asm volatile("cp.async.commit_group;" ::: "memory");
}
__device__ __forceinline__ void ldsm4(uint32_t r[4], uint32_t addr) {
    asm volatile("ldmatrix.sync.aligned.m8n8.x4.shared.b16 {%0,%1,%2,%3}, [%4];"
                 : "=r"(r[0]), "=r"(r[1]), "=r"(r[2]), "=r"(r[3]) : "r"(addr));
}
__device__ __forceinline__ void mma_tf32(float d[4], const uint32_t a[4],
                                         const uint32_t b[2], const float c[4]) {
    asm volatile(
        "mma.sync.aligned.m16n8k8.row.col.f32.tf32.tf32.f32 "
        "{%0,%1,%2,%3}, {%4,%5,%6,%7}, {%8,%9}, {%10,%11,%12,%13};\n"
        : "=f"(d[0]), "=f"(d[1]), "=f"(d[2]), "=f"(d[3])
        : "r"(a[0]), "r"(a[1]), "r"(a[2]), "r"(a[3]),
          "r"(b[0]), "r"(b[1]),
          "f"(c[0]), "f"(c[1]), "f"(c[2]), "f"(c[3]));
}

// ---------------------------------------------------------------------------
// Variant A (short-K GEMMs): 256 threads, 4x2 warps, 32x(BN/2) warp tiles.
//   EPI 0: raw+bias   EPI 4: fused gates
// ---------------------------------------------------------------------------
template <int EPI, int BN>
__global__ __launch_bounds__(256, 2) void tgemm(
    const float* __restrict__ A, const float* __restrict__ B,
    const float* __restrict__ bias, float* __restrict__ C,
    float* __restrict__ C2, const float* __restrict__ Xbc,
    const float* __restrict__ lam, int M, int N, int K)
{
    constexpr int NI = BN / 16;
    constexpr int NP = BN / 32;
    constexpr int ABYTES = 128 * BKF * 4;
    constexpr int BBYTES = BN * BKF * 4;
    constexpr int SBYTES = ABYTES + BBYTES;

    extern __shared__ char dynsm[];
    const uint32_t sb = (smem_u32(dynsm) + 1023u) & ~1023u;

    const int tid  = threadIdx.x;
    const int lane = tid & 31;
    const int wid  = tid >> 5;
    const int bm   = blockIdx.y * 128;
    const int bn   = blockIdx.x * BN;
    const int wm   = (wid >> 1) * 32;
    const int wn   = (wid & 1) * (BN / 2);
    const int qr   = lane >> 2;
    const int qc   = lane & 3;

    const int arow  = wm + (lane & 15);
    const int ahalf = (lane >> 4) & 1;
    const int brow  = wn + (lane & 7) + ((lane >> 4) << 3);
    const int bhalf = (lane >> 3) & 1;

    float acc[2][NI][4];
#pragma unroll
    for (int mi = 0; mi < 2; mi++)
#pragma unroll
        for (int ni = 0; ni < NI; ni++)
#pragma unroll
            for (int r = 0; r < 4; r++) acc[mi][ni][r] = 0.0f;

    const int nch = K / BKF;

    auto issue_chunk = [&](int c) {
        const int s = c % NSTAGE;
        const uint32_t abase = sb + s * SBYTES;
        const uint32_t bbase = abase + ABYTES;
        const int k0 = c * BKF;
#pragma unroll
        for (int q = 0; q < 4; q++) {
            int id  = tid + q * 256;
            int row = id >> 3;
            int c16 = id & 7;
            cp16(abase + SW128(row * 128 + c16 * 16),
                 A + (size_t)(bm + row) * K + k0 + c16 * 4);
        }
#pragma unroll
        for (int q = 0; q < NP; q++) {
            int id  = tid + q * 256;
            int row = id >> 3;
            int c16 = id & 7;
            cp16(bbase + SW128(row * 128 + c16 * 16),
                 B + (size_t)(bn + row) * K + k0 + c16 * 4);
        }
        cp_commit();
    };

    auto compute = [&](int s) {
        const uint32_t abase = sb + s * SBYTES;
        const uint32_t bbase = abase + ABYTES;
#pragma unroll
        for (int kb = 0; kb < 4; kb++) {
            uint32_t af[2][4];
#pragma unroll
            for (int mi = 0; mi < 2; mi++)
                ldsm4(af[mi], abase + SW128((arow + mi * 16) * 128 + kb * 32 + ahalf * 16));
            uint32_t bf[NP][4];
#pragma unroll
            for (int p = 0; p < NP; p++)
                ldsm4(bf[p], bbase + SW128((brow + p * 16) * 128 + kb * 32 + bhalf * 16));
#pragma unroll
            for (int mi = 0; mi < 2; mi++)
#pragma unroll
                for (int ni = 0; ni < NI; ni++)
                    mma_tf32(acc[mi][ni], af[mi], &bf[ni >> 1][(ni & 1) * 2], acc[mi][ni]);
        }
    };

    // mainloop: split tail (race-free)
    issue_chunk(0);
    issue_chunk(1);
    for (int c = 0; c < nch - 1; c++) {
        asm volatile("cp.async.wait_group %0;" :: "n"(1) : "memory");
        __syncthreads();
        if (c + 2 < nch) issue_chunk(c + 2);
        compute(c % NSTAGE);
    }
    asm volatile("cp.async.wait_group %0;" :: "n"(0) : "memory");
    __syncthreads();
    compute((nch - 1) % NSTAGE);

#pragma unroll
    for (int mi = 0; mi < 2; mi++) {
#pragma unroll
        for (int ni = 0; ni < NI; ni++) {
#pragma unroll
            for (int half = 0; half < 2; half++) {
                int m = bm + wm + mi * 16 + qr + half * 8;
                int n = bn + wn + ni * 8 + 2 * qc;
                if (EPI == 0) {
                    C[(size_t)m * N + n]     = acc[mi][ni][half * 2 + 0] + bias[n];
                    C[(size_t)m * N + n + 1] = acc[mi][ni][half * 2 + 1] + bias[n + 1];
                } else {  // EPI == 4 : fused gate pair (inp, rec) for channel n>>1
                    float v0  = acc[mi][ni][half * 2 + 0] + bias[n];
                    float v1  = acc[mi][ni][half * 2 + 1] + bias[n + 1];
                    int ch    = n >> 1;
                    float inp = sigm(v0);
                    float rec = sigm(v1);
                    float a   = __expf(lam[ch] * rec);
                    float gx  = sqrtf(fmaxf(1.0f - a * a, 0.0f)) * inp *
                                Xbc[(size_t)m * DR + ch];
                    C[(size_t)m * DR + ch]  = a;
                    C2[(size_t)m * DR + ch] = gx;
                }
            }
        }
    }
}

// ---------------------------------------------------------------------------
// Weight-compose GEMM: W'_tap = Wk_dup @ [hi|lo]^T over K=2048.
// grid (6, 8, 4): N=768, M=1024, tap=z. C row stride 3072, tap block offset.
// ---------------------------------------------------------------------------
__global__ __launch_bounds__(256, 2) void wgemm_kernel()
{
    constexpr int BN = 128, NI = 8, NP = 4, K = 2048;
    constexpr int ABYTES = 128 * BKF * 4;
    constexpr int SBYTES = ABYTES + BN * BKF * 4;

    extern __shared__ char dynsm[];
    const uint32_t sb = (smem_u32(dynsm) + 1023u) & ~1023u;

    const float* A = g_wck + (size_t)blockIdx.z * DR * 2048;
    const float* B = g_w1bt;
    float* C       = g_wcomb + (size_t)blockIdx.z * DM;

    const int tid  = threadIdx.x;
    const int lane = tid & 31;
    const int wid  = tid >> 5;
    const int bm   = blockIdx.y * 128;
    const int bn   = blockIdx.x * BN;
    const int wm   = (wid >> 1) * 32;
    const int wn   = (wid & 1) * 64;
    const int qr   = lane >> 2;
    const int qc   = lane & 3;

    const int arow  = wm + (lane & 15);
    const int ahalf = (lane >> 4) & 1;
    const int brow  = wn + (lane & 7) + ((lane >> 4) << 3);
    const int bhalf = (lane >> 3) & 1;

    float acc[2][NI][4];
#pragma unroll
    for (int mi = 0; mi < 2; mi++)
#pragma unroll
        for (int ni = 0; ni < NI; ni++)
#pragma unroll
            for (int r = 0; r < 4; r++) acc[mi][ni][r] = 0.0f;

    const int nch = K / BKF;

    auto issue_chunk = [&](int c) {
        const int s = c % NSTAGE;
        const uint32_t abase = sb + s * SBYTES;
        const uint32_t bbase = abase + ABYTES;
        const int k0 = c * BKF;
#pragma unroll
        for (int q = 0; q < 4; q++) {
            int id  = tid + q * 256;
            int row = id >> 3;
            int c16 = id & 7;
            cp16(abase + SW128(row * 128 + c16 * 16),
                 A + (size_t)(bm + row) * K + k0 + c16 * 4);
        }
#pragma unroll
        for (int q = 0; q < NP; q++) {
            int id  = tid + q * 256;
            int row = id >> 3;
            int c16 = id & 7;
            cp16(bbase + SW128(row * 128 + c16 * 16),
                 B + (size_t)(bn + row) * K + k0 + c16 * 4);
        }
        cp_commit();
    };

    auto compute = [&](int s) {
        const uint32_t abase = sb + s * SBYTES;
        const uint32_t bbase = abase + ABYTES;
#pragma unroll
        for (int kb = 0; kb < 4; kb++) {
            uint32_t af[2][4];
#pragma unroll
            for (int mi = 0; mi < 2; mi++)
                ldsm4(af[mi], abase + SW128((arow + mi * 16) * 128 + kb * 32 + ahalf * 16));
            uint32_t bf[NP][4];
#pragma unroll
            for (int p = 0; p < NP; p++)
                ldsm4(bf[p], bbase + SW128((brow + p * 16) * 128 + kb * 32 + bhalf * 16));
#pragma unroll
            for (int mi = 0; mi < 2; mi++)
#pragma unroll
                for (int ni = 0; ni < NI; ni++)
                    mma_tf32(acc[mi][ni], af[mi], &bf[ni >> 1][(ni & 1) * 2], acc[mi][ni]);
        }
    };

    issue_chunk(0);
    issue_chunk(1);
    for (int c = 0; c < nch - 1; c++) {
        asm volatile("cp.async.wait_group %0;" :: "n"(1) : "memory");
        __syncthreads();
        if (c + 2 < nch) issue_chunk(c + 2);
        compute(c % NSTAGE);
    }
    asm volatile("cp.async.wait_group %0;" :: "n"(0) : "memory");
    __syncthreads();
    compute((nch - 1) % NSTAGE);

#pragma unroll
    for (int mi = 0; mi < 2; mi++) {
#pragma unroll
        for (int ni = 0; ni < NI; ni++) {
#pragma unroll
            for (int half = 0; half < 2; half++) {
                int m = bm + wm + mi * 16 + qr + half * 8;
                int n = bn + wn + ni * 8 + 2 * qc;
                C[(size_t)m * 3072 + n]     = roundtf(acc[mi][ni][half * 2 + 0]);
                C[(size_t)m * 3072 + n + 1] = roundtf(acc[mi][ni][half * 2 + 1]);
            }
        }
    }
}

// ---------------------------------------------------------------------------
// Merged heterogeneous kernel: 128 threads, 2x2 warps, 64x64 warp tiles.
//   blockIdx.x < conv_tiles : composed conv tile (A = padded x, K=3072;
//                             + cb (- cpart rows 0..2), round -> g_bcr)
//   else                    : gemm1-ab tile (A = x, K=768; bias+gelu -> g_ab)
// Both duties read A with row stride DM (conv's taps are K-contiguous).
// ---------------------------------------------------------------------------
__global__ __launch_bounds__(128, 2) void tgemm_merged(
    const float* __restrict__ Axp, const float* __restrict__ Bwc,
    const float* __restrict__ cb, const float* __restrict__ cpart,
    float* __restrict__ Cbc,
    const float* __restrict__ Bw1a, const float* __restrict__ bias1,
    float* __restrict__ Cab, int conv_tiles)
{
    constexpr int SBYTES = 2 * 128 * BKF * 4;
    extern __shared__ char dynsm[];
    const uint32_t sb = (smem_u32(dynsm) + 1023u) & ~1023u;

    const bool isconv = ((int)blockIdx.x) < conv_tiles;
    const int  tile   = isconv ? blockIdx.x : (blockIdx.x - conv_tiles);
    const int  bn     = (tile & 7) * 128;
    const int  bm     = (tile >> 3) * 128;
    const int  K      = isconv ? 3072 : DM;
    const float* Abase = isconv ? Axp : (Axp + 3 * DM);
    const float* B     = isconv ? Bwc : Bw1a;

    const int tid  = threadIdx.x;
    const int wid  = tid >> 5;
    const int lane = tid & 31;
    const int wm   = (wid >> 1) * 64;
    const int wn   = (wid & 1) * 64;
    const int qr   = lane >> 2;
    const int qc   = lane & 3;

    const int arow  = wm + (lane & 15);
    const int ahalf = (lane >> 4) & 1;
    const int brow  = wn + (lane & 7) + ((lane >> 4) << 3);
    const int bhalf = (lane >> 3) & 1;

    float acc[4][8][4];
#pragma unroll
    for (int mi = 0; mi < 4; mi++)
#pragma unroll
        for (int ni = 0; ni < 8; ni++)
#pragma unroll
            for (int r = 0; r < 4; r++) acc[mi][ni][r] = 0.0f;

    const int nch = K / BKF;

    auto issue_chunk = [&](int c) {
        const int s = c % NSTAGE;
        const uint32_t abase = sb + s * SBYTES;
        const uint32_t bbase = abase + 128 * BKF * 4;
        const int k0 = c * BKF;
#pragma unroll
        for (int q = 0; q < 8; q++) {
            int id  = tid + q * 128;
            int row = id >> 3;
            int c16 = id & 7;
            cp16(abase + SW128(row * 128 + c16 * 16),
                 Abase + (size_t)(bm + row) * DM + k0 + c16 * 4);
            cp16(bbase + SW128(row * 128 + c16 * 16),
                 B + (size_t)(bn + row) * K + k0 + c16 * 4);
        }
        cp_commit();
    };

    auto compute = [&](int s) {
        const uint32_t abase = sb + s * SBYTES;
        const uint32_t bbase = abase + 128 * BKF * 4;
#pragma unroll
        for (int kb = 0; kb < 4; kb++) {
            uint32_t af[4][4];
#pragma unroll
            for (int mi = 0; mi < 4; mi++)
                ldsm4(af[mi], abase + SW128((arow + mi * 16) * 128 + kb * 32 + ahalf * 16));
            uint32_t bf[4][4];
#pragma unroll
            for (int p = 0; p < 4; p++)
                ldsm4(bf[p], bbase + SW128((brow + p * 16) * 128 + kb * 32 + bhalf * 16));
#pragma unroll
            for (int mi = 0; mi < 4; mi++)
#pragma unroll
                for (int ni = 0; ni < 8; ni++)
                    mma_tf32(acc[mi][ni], af[mi], &bf[ni >> 1][(ni & 1) * 2], acc[mi][ni]);
        }
    };

    // mainloop: issue-first + split tail (race-free)
    issue_chunk(0);
    issue_chunk(1);
    for (int c = 0; c < nch - 1; c++) {
        asm volatile("cp.async.wait_group %0;" :: "n"(1) : "memory");
        __syncthreads();
        if (c + 2 < nch) issue_chunk(c + 2);
        compute(c % NSTAGE);
    }
    asm volatile("cp.async.wait_group %0;" :: "n"(0) : "memory");
    __syncthreads();
    compute((nch - 1) % NSTAGE);

#pragma unroll
    for (int mi = 0; mi < 4; mi++) {
#pragma unroll
        for (int ni = 0; ni < 8; ni++) {
#pragma unroll
            for (int half = 0; half < 2; half++) {
                int m = bm + wm + mi * 16 + qr + half * 8;
                int n = bn + wn + ni * 8 + 2 * qc;
                float v0 = acc[mi][ni][half * 2 + 0];
                float v1 = acc[mi][ni][half * 2 + 1];
                if (isconv) {
                    v0 += cb[n];
                    v1 += cb[n + 1];
                    if (m < 3) {                     // only the bm==0 tiles
                        v0 -= cpart[m * DR + n];
                        v1 -= cpart[m * DR + n + 1];
                    }
                    Cbc[(size_t)m * DR + n]     = roundtf(v0);
                    Cbc[(size_t)m * DR + n + 1] = roundtf(v1);
                } else {
                    Cab[(size_t)m * DR + n]     = gelu_f(v0 + bias1[n]);
                    Cab[(size_t)m * DR + n + 1] = gelu_f(v1 + bias1[n + 1]);
                }
            }
        }
    }
}

// ---------------------------------------------------------------------------
// prep (single kernel). Bias vectors via warp-per-output reduction (fast).
__global__ void prep_kernel(const float* __restrict__ wrg,
                            const float* __restrict__ brg,
                            const float* __restrict__ Lambda,
                            const float* __restrict__ convw,
                            const float* __restrict__ x,
                            const float* __restrict__ w1,
                            const float* __restrict__ wout,
                            const float* __restrict__ b1) {
    int gid = blockIdx.x * blockDim.x + threadIdx.x;
    if (gid < 2 * DR) g_brgp[gid] = brg[(gid & 1) ? (DR + (gid >> 1)) : (gid >> 1)];
    if (gid < DR)     g_lam[gid]  = -8.0f * log1pf(expf(Lambda[gid]));
    // conv bias vectors: warp w handles output o=w, lanes stride channels
    if (gid < 32 * DR) {
        int o    = gid >> 5;
        int lane = gid & 31;
        const float* b1b = b1 + DR;
        float full = 0.f, p0 = 0.f, p1 = 0.f, p2 = 0.f;
        for (int i = lane; i < DR; i += 32) {
            float4 w = *reinterpret_cast<const float4*>(&convw[((size_t)o * DR + i) * 4]);
            float bi = b1b[i];
            full = fmaf(w.x + w.y + w.z + w.w, bi, full);
            p0   = fmaf(w.x + w.y + w.z, bi, p0);
            p1   = fmaf(w.x + w.y, bi, p1);
            p2   = fmaf(w.x, bi, p2);
        }
#pragma unroll
        for (int off = 16; off > 0; off >>= 1) {
            full += __shfl_down_sync(0xffffffffu, full, off);
            p0   += __shfl_down_sync(0xffffffffu, p0,   off);
            p1   += __shfl_down_sync(0xffffffffu, p1,   off);
            p2   += __shfl_down_sync(0xffffffffu, p2,   off);
        }
        if (lane == 0) {
            g_cb[o] = full;
            g_cpart[0 * DR + o] = p0;
            g_cpart[1 * DR + o] = p1;
            g_cpart[2 * DR + o] = p2;
        }
    }
    // w_rg row permute (float4 over k)
    if (gid < 2 * DR * DR / 4) {
        int r  = gid >> 8;
        int k4 = gid & 255;
        int srcr = (r & 1) ? (DR + (r >> 1)) : (r >> 1);
        float4 v = *reinterpret_cast<const float4*>(&wrg[(size_t)srcr * DR + k4 * 4]);
        v.x = roundtf(v.x); v.y = roundtf(v.y); v.z = roundtf(v.z); v.w = roundtf(v.w);
        *reinterpret_cast<float4*>(&g_wrgp[(size_t)r * DR + k4 * 4]) = v;
    }
    // conv tap repack -> duplicated [Wk|Wk], rounded (coalesced writes)
    if (gid < DR * DR) {
        int o = gid >> 10;
        int i = gid & 1023;
        float4 v = *reinterpret_cast<const float4*>(&convw[(size_t)gid * 4]);
        float t0 = roundtf(v.x), t1 = roundtf(v.y), t2 = roundtf(v.z), t3 = roundtf(v.w);
        size_t b = (size_t)o * 2048 + i;
        g_wck[0 * (size_t)DR * 2048 + b] = t0; g_wck[0 * (size_t)DR * 2048 + b + 1024] = t0;
        g_wck[1 * (size_t)DR * 2048 + b] = t1; g_wck[1 * (size_t)DR * 2048 + b + 1024] = t1;
        g_wck[2 * (size_t)DR * 2048 + b] = t2; g_wck[2 * (size_t)DR * 2048 + b + 1024] = t2;
        g_wck[3 * (size_t)DR * 2048 + b] = t3; g_wck[3 * (size_t)DR * 2048 + b + 1024] = t3;
    }
    // w1b^T hi/lo split (coalesced WRITES: consecutive gid -> consecutive i)
    if (gid < DM * DR) {
        int j = gid >> 10;         // x-dim 0..767
        int i = gid & 1023;        // channel 0..1023
        float w  = w1[(size_t)(DR + i) * DM + j];
        float hi = roundtf(w);
        float lo = roundtf(w - hi);
        g_w1bt[(size_t)j * 2048 + i]        = hi;
        g_w1bt[(size_t)j * 2048 + 1024 + i] = lo;
    }
    // rounding copies: x -> g_xpr (+3 zero rows already zero), w1, wout
    {
        const int nx = T_LEN * DM / 4, n1 = 2 * DR * DM / 4, n2 = DM * DR / 4;
        const float4* s = nullptr; float4* d = nullptr; int i = 0;
        if (gid < nx)                { s = (const float4*)x;    d = (float4*)(g_xpr + 3 * DM); i = gid; }
        else if (gid < nx + n1)      { s = (const float4*)w1;   d = (float4*)g_w1r;   i = gid - nx; }
        else if (gid < nx + n1 + n2) { s = (const float4*)wout; d = (float4*)g_woutr; i = gid - nx - n1; }
        if (s) {
            float4 v = s[i];
            v.x = roundtf(v.x); v.y = roundtf(v.y); v.z = roundtf(v.z); v.w = roundtf(v.w);
            d[i] = v;
        }
    }
}

// ---- 3-phase chunked linear scan (float4 over channels; 256 chunks of 32) ----
__global__ void scan_phaseA_kernel() {
    int g = blockIdx.x * blockDim.x + threadIdx.x;
    if (g >= NCHK * DR / 4) return;
    int c4 = (g & (DR / 4 - 1)) * 4;
    int ch = g / (DR / 4);
    size_t base = (size_t)ch * CLEN * DR + c4;
    float4 P = make_float4(1.f, 1.f, 1.f, 1.f);
    float4 L = make_float4(0.f, 0.f, 0.f, 0.f);
#pragma unroll 4
    for (int t = 0; t < CLEN; t++) {
        float4 a = *reinterpret_cast<const float4*>(&g_at[base + (size_t)t * DR]);
        float4 x = *reinterpret_cast<const float4*>(&g_gx[base + (size_t)t * DR]);
        L.x = fmaf(a.x, L.x, x.x); L.y = fmaf(a.y, L.y, x.y);
        L.z = fmaf(a.z, L.z, x.z); L.w = fmaf(a.w, L.w, x.w);
        P.x *= a.x; P.y *= a.y; P.z *= a.z; P.w *= a.w;
    }
    *reinterpret_cast<float4*>(&g_P[ch * DR + c4]) = P;
    *reinterpret_cast<float4*>(&g_L[ch * DR + c4]) = L;
}

__global__ void scan_phaseB_kernel() {
    int c4 = (blockIdx.x * blockDim.x + threadIdx.x) * 4;
    if (c4 >= DR) return;
    float4 carry = make_float4(0.f, 0.f, 0.f, 0.f);
    for (int ch = 0; ch < NCHK; ch++) {
        *reinterpret_cast<float4*>(&g_carry[ch * DR + c4]) = carry;
        float4 P = *reinterpret_cast<const float4*>(&g_P[ch * DR + c4]);
        float4 L = *reinterpret_cast<const float4*>(&g_L[ch * DR + c4]);
        carry.x = fmaf(P.x, carry.x, L.x); carry.y = fmaf(P.y, carry.y, L.y);
        carry.z = fmaf(P.z, carry.z, L.z); carry.w = fmaf(P.w, carry.w, L.w);
    }
}

__global__ void scan_phaseC_kernel() {
    int g = blockIdx.x * blockDim.x + threadIdx.x;
    if (g >= NCHK * DR / 4) return;
    int c4 = (g & (DR / 4 - 1)) * 4;
    int ch = g / (DR / 4);
    size_t base = (size_t)ch * CLEN * DR + c4;
    float4 h = *reinterpret_cast<const float4*>(&g_carry[ch * DR + c4]);
#pragma unroll 4
    for (int t = 0; t < CLEN; t++) {
        size_t o = base + (size_t)t * DR;
        float4 a  = *reinterpret_cast<const float4*>(&g_at[o]);
        float4 x  = *reinterpret_cast<const float4*>(&g_gx[o]);
        float4 ab = *reinterpret_cast<const float4*>(&g_ab[o]);
        h.x = fmaf(a.x, h.x, x.x); h.y = fmaf(a.y, h.y, x.y);
        h.z = fmaf(a.z, h.z, x.z); h.w = fmaf(a.w, h.w, x.w);
        float4 z;
        z.x = roundtf(ab.x * h.x); z.y = roundtf(ab.y * h.y);
        z.z = roundtf(ab.z * h.z); z.w = roundtf(ab.w * h.w);
        *reinterpret_cast<float4*>(&g_z[o]) = z;
    }
}

// ---------------------------------------------------------------------------
extern "C" void kernel_launch(void* const* d_in, const int* in_sizes, int n_in,
                              void* d_out, int out_size)
{
    const float* x      = (const float*)d_in[0];
    const float* w1     = (const float*)d_in[1];
    const float* b1     = (const float*)d_in[2];
    const float* conv_w = (const float*)d_in[3];
    const float* w_rg   = (const float*)d_in[4];
    const float* b_rg   = (const float*)d_in[5];
    const float* w_out  = (const float*)d_in[6];
    const float* b_out  = (const float*)d_in[7];
    const float* Lambda = (const float*)d_in[8];
    float* out = (float*)d_out;

    float *p_ab, *p_bcr, *p_at, *p_gx, *p_z, *p_xpr, *p_w1r, *p_wcomb;
    float *p_wrgp, *p_brgp, *p_woutr, *p_lam, *p_cb, *p_cpart;
    cudaGetSymbolAddress((void**)&p_ab,    g_ab);
    cudaGetSymbolAddress((void**)&p_bcr,   g_bcr);
    cudaGetSymbolAddress((void**)&p_at,    g_at);
    cudaGetSymbolAddress((void**)&p_gx,    g_gx);
    cudaGetSymbolAddress((void**)&p_z,     g_z);
    cudaGetSymbolAddress((void**)&p_xpr,   g_xpr);
    cudaGetSymbolAddress((void**)&p_w1r,   g_w1r);
    cudaGetSymbolAddress((void**)&p_wcomb, g_wcomb);
    cudaGetSymbolAddress((void**)&p_wrgp,  g_wrgp);
    cudaGetSymbolAddress((void**)&p_brgp,  g_brgp);
    cudaGetSymbolAddress((void**)&p_woutr, g_woutr);
    cudaGetSymbolAddress((void**)&p_lam,   g_lam);
    cudaGetSymbolAddress((void**)&p_cb,    g_cb);
    cudaGetSymbolAddress((void**)&p_cpart, g_cpart);

    const int smem128 = NSTAGE * (128 + 128) * BKF * 4 + 1024;
    const int smem64  = NSTAGE * (128 + 64)  * BKF * 4 + 1024;
    cudaFuncSetAttribute(wgemm_kernel,  cudaFuncAttributeMaxDynamicSharedMemorySize, smem128);
    cudaFuncSetAttribute(tgemm_merged,  cudaFuncAttributeMaxDynamicSharedMemorySize, smem128);
    cudaFuncSetAttribute(tgemm<4, 128>, cudaFuncAttributeMaxDynamicSharedMemorySize, smem128);
    cudaFuncSetAttribute(tgemm<0, 64>,  cudaFuncAttributeMaxDynamicSharedMemorySize, smem64);

    // #1 prep
    {
        int total = T_LEN * DM / 4 + 2 * DR * DM / 4 + DM * DR / 4;   // widest range
        prep_kernel<<<(total + 255) / 256, 256>>>(w_rg, b_rg, Lambda, conv_w,
                                                  x, w1, w_out, b1);
    }
    // #2 weight-compose GEMM (4 taps in one launch; one wave)
    {
        dim3 grid(DM / 128, DR / 128, 4);
        wgemm_kernel<<<grid, 256, smem128>>>();
    }
    // #3 merged: composed-conv tiles (512, first) + gemm1 ab-half tiles (512)
    {
        tgemm_merged<<<1024, 128, smem128>>>(p_xpr, p_wcomb, p_cb, p_cpart, p_bcr,
                                             p_w1r, b1, p_ab, 512);
    }
    // #4 gemm3 + fused gates
    {
        dim3 grid((2 * DR) / 128, T_LEN / 128);
        tgemm<4, 128><<<grid, 256, smem128>>>(p_bcr, p_wrgp, p_brgp, p_at, p_gx,
                                              p_bcr, p_lam, T_LEN, 2 * DR, DR);
    }
    scan_phaseA_kernel<<<(NCHK * DR / 4 + 255) / 256, 256>>>();
    scan_phaseB_kernel<<<(DR / 4 + 255) / 256, 256>>>();
    scan_phaseC_kernel<<<(NCHK * DR / 4 + 255) / 256, 256>>>();
    // #8 gemm4 (BN=64)
    {
        dim3 grid(DM / 64, T_LEN / 128);
        tgemm<0, 64><<<grid, 256, smem64>>>(p_z, p_woutr, b_out, out, nullptr,
                                            nullptr, nullptr, T_LEN, DM, DR);
    }
}